// round 7
// baseline (speedup 1.0000x reference)
#include <cuda_runtime.h>
#include <cuda_bf16.h>

#define N_NODES 10000
#define NQUERY  65536

__global__ __launch_bounds__(256, 5)
void madgraph_kernel(const int* __restrict__ src,
                     const int* __restrict__ dst,
                     const int* __restrict__ mid0,
                     const int* __restrict__ mid1,
                     const float* __restrict__ position,
                     const float* __restrict__ src_field,
                     const float* __restrict__ dst_field,
                     const float* __restrict__ unc,
                     const float* __restrict__ edge,
                     float* __restrict__ out)
{
    const unsigned FULL = 0xFFFFFFFFu;
    const int warp = (blockIdx.x * blockDim.x + threadIdx.x) >> 5;
    const int lane = threadIdx.x & 31;
    if (warp >= NQUERY) return;
    const int n = warp;

    const int hl      = lane & 15;   // lane within half-warp
    const int halfSel = lane & 16;   // 0 = pass1 (src side), 16 = pass2 (dst side)

    const int s_node = __ldg(&src[n]);
    const int d_node = __ldg(&dst[n]);

    // Mid holders: lanes 0-7 -> mid0[hl], lanes 16-23 -> mid1[hl].
    int m_own = 0;
    if ((lane & 8) == 0)
        m_own = halfSel ? __ldg(&mid1[n * 8 + hl]) : __ldg(&mid0[n * 8 + hl]);

    // Edge value on owner lanes (DRAM-resident, issue early).
    float ev = 0.f;
    if ((lane & 8) == 0) {
        const int eidx = halfSel ? (s_node * N_NODES + m_own)    // edge[src, mid1[s]]
                                 : (m_own * N_NODES + d_node);   // edge[mid0[s], dst]
        ev = __ldg(&edge[eidx]);
    }
    const float u = __ldg(unc);

    const float4* pos4 = (const float4*)position;
    const int baseRow = halfSel ? d_node : s_node;               // pos[dst] / pos[src]
    const float4* frow = halfSel ? ((const float4*)src_field) + s_node * 32
                                 : ((const float4*)dst_field) + d_node * 32;

    // V[s]   = dot partial for this half's sample s   (s = 0..7)
    // V[8+s] = squared-norm partial for sample s
    float V[16];
    #pragma unroll
    for (int i = 0; i < 16; ++i) V[i] = 0.f;

    #pragma unroll
    for (int phase = 0; phase < 2; ++phase) {       // two float4 columns per lane
        const int c0 = hl + phase * 16;
        const float4 base = __ldg(&pos4[baseRow * 32 + c0]);
        const float4 f    = __ldg(&frow[c0]);
        #pragma unroll
        for (int ch = 0; ch < 2; ++ch) {            // 4-sample chunks (reg budget)
            int mm[4]; float4 pm[4];
            #pragma unroll
            for (int j = 0; j < 4; ++j)
                mm[j] = __shfl_sync(FULL, m_own, (ch * 4 + j) | halfSel);
            #pragma unroll
            for (int j = 0; j < 4; ++j)
                pm[j] = __ldg(&pos4[mm[j] * 32 + c0]);
            #pragma unroll
            for (int j = 0; j < 4; ++j) {
                const int s = ch * 4 + j;
                const float dx = base.x - pm[j].x, dy = base.y - pm[j].y;
                const float dz = base.z - pm[j].z, dw = base.w - pm[j].w;
                V[s]     += dx * f.x + dy * f.y + dz * f.z + dw * f.w;
                V[8 + s] += dx * dx  + dy * dy  + dz * dz  + dw * dw;
            }
        }
    }

    // 16-value butterfly per half-warp (offsets 8,4,2,1 stay within each half).
    // Identity mapping: lane with half-index hl ends holding value index hl.
    #pragma unroll
    for (int m = 8, cnt = 16; m >= 1; m >>= 1, cnt >>= 1) {
        const int  half  = cnt >> 1;
        const bool upper = (lane & m) != 0;
        #pragma unroll
        for (int j = 0; j < 8; ++j) {
            if (j < half) {
                float send = upper ? V[j] : V[j + half];
                float recv = __shfl_xor_sync(FULL, send, m);
                V[j] = (upper ? V[j + half] : V[j]) + recv;
            }
        }
    }
    const float D = V[0];                         // hl<8: dot_hl ; hl>=8: n2_{hl-8}
    const float M = __shfl_xor_sync(FULL, D, 8);  // owner lanes receive their n2

    // Owners: lanes 0-7 (samples 0-7) and 16-23 (samples 8-15).
    float a, logit;
    if ((lane & 8) == 0) {
        logit = D + u * ev;
        a = 1.0f - sqrtf(M);
    } else {
        logit = 0.f;
        a = -1e30f;
    }

    // Full-warp value-neutral softmax reduce over the 16 owner lanes.
    float mx = a;
    #pragma unroll
    for (int o = 16; o > 0; o >>= 1)
        mx = fmaxf(mx, __shfl_xor_sync(FULL, mx, o));

    const float e = ((lane & 8) == 0) ? __expf(a - mx) : 0.f;
    float num = logit * e;
    float den = e;
    #pragma unroll
    for (int o = 16; o > 0; o >>= 1) {
        num += __shfl_xor_sync(FULL, num, o);
        den += __shfl_xor_sync(FULL, den, o);
    }

    if (lane == 0) out[n] = num / den;
}

extern "C" void kernel_launch(void* const* d_in, const int* in_sizes, int n_in,
                              void* d_out, int out_size)
{
    const int*   src      = (const int*)  d_in[0];
    const int*   dst      = (const int*)  d_in[1];
    const int*   mid0     = (const int*)  d_in[2];
    const int*   mid1     = (const int*)  d_in[3];
    const float* position = (const float*)d_in[4];
    const float* src_f    = (const float*)d_in[5];
    const float* dst_f    = (const float*)d_in[6];
    const float* unc      = (const float*)d_in[7];
    const float* edge     = (const float*)d_in[8];
    float*       out      = (float*)      d_out;

    const int blocks = NQUERY / 8;   // 8 warps (queries) per 256-thread block
    madgraph_kernel<<<blocks, 256>>>(src, dst, mid0, mid1, position,
                                     src_f, dst_f, unc, edge, out);
}